// round 6
// baseline (speedup 1.0000x reference)
#include <cuda_runtime.h>
#include <cuda_fp16.h>
#include <math.h>
#include <cstdint>

#define N_NODES 50000
#define N_EDGES 800000
#define NKC     4096        // NK * COUT = 64*64
#define NSEG    8192        // NB * GRID^3
#define EPS_BN  1e-5f
#define NBKT    3200        // src buckets (src>>4): 3125 used

// ---------------- device scratch ----------------
__device__ __half g_xw[(long long)N_NODES * NKC];   // 410 MB fp16: x @ W_k
__device__ __half g_xh[N_NODES * 64];               // x in fp16
__device__ __half g_wt[NKC * 64];                   // transposed weight [col][c] fp16
__device__ float g_agg[N_NODES * 64];
__device__ float g_h[N_NODES * 64];
__device__ float g_cnt[N_NODES];
__device__ float g_stats[128];
__device__ float g_scale[64];
__device__ float g_shift[64];
__device__ unsigned g_bcnt[NBKT + 64];
__device__ unsigned g_boff[NBKT + 64];
__device__ float4 g_rec[N_EDGES];                   // t0,t1,t2, bits(src | base_k<<20)
__device__ int    g_rdst[N_EDGES];

// ---------------- helpers ----------------
__device__ __forceinline__ unsigned encf(float f) {
    unsigned u = __float_as_uint(f);
    return (u & 0x80000000u) ? ~u : (u | 0x80000000u);
}
__device__ __forceinline__ float decf(unsigned e) {
    return __uint_as_float((e & 0x80000000u) ? (e ^ 0x80000000u) : ~e);
}
__device__ __forceinline__ void red_add_v4(float* p, float a, float b, float c, float d) {
    asm volatile("red.global.add.v4.f32 [%0], {%1, %2, %3, %4};"
                 :: "l"(p), "f"(a), "f"(b), "f"(c), "f"(d) : "memory");
}
__device__ __forceinline__ void red_add_f32(float* p, float a) {
    asm volatile("red.global.add.f32 [%0], %1;" :: "l"(p), "f"(a) : "memory");
}
__device__ __forceinline__ void hmma16816(float* d, const uint32_t* a, const uint32_t* b) {
    asm volatile(
        "mma.sync.aligned.m16n8k16.row.col.f32.f16.f16.f32 "
        "{%0,%1,%2,%3}, {%4,%5,%6,%7}, {%8,%9}, {%0,%1,%2,%3};"
        : "+f"(d[0]), "+f"(d[1]), "+f"(d[2]), "+f"(d[3])
        : "r"(a[0]), "r"(a[1]), "r"(a[2]), "r"(a[3]), "r"(b[0]), "r"(b[1]));
}
__device__ __forceinline__ void ldsm_x4(uint32_t* r, uint32_t addr) {
    asm volatile("ldmatrix.sync.aligned.m8n8.x4.shared.b16 {%0,%1,%2,%3}, [%4];"
                 : "=r"(r[0]), "=r"(r[1]), "=r"(r[2]), "=r"(r[3]) : "r"(addr));
}
__device__ __forceinline__ uint32_t smem_u32(const void* p) {
    uint32_t a;
    asm("{ .reg .u64 t; cvta.to.shared.u64 t, %1; cvt.u32.u64 %0, t; }" : "=r"(a) : "l"(p));
    return a;
}

// ---------------- init ----------------
__global__ void init_kernel(unsigned* __restrict__ out) {
    int i = blockIdx.x * 256 + threadIdx.x;
    if (i < N_NODES * 64) g_agg[i] = 0.f;
    if (i < N_NODES)      g_cnt[i] = 0.f;
    if (i < 128)          g_stats[i] = 0.f;
    if (i < NBKT + 64)    g_bcnt[i] = 0u;
    if (i < NSEG * 64)    out[i] = 0u;
}

// ---------------- fp16 conversions ----------------
__global__ void cvt_x_kernel(const float* __restrict__ x) {
    int i = blockIdx.x * 256 + threadIdx.x;
    if (i < N_NODES * 64) g_xh[i] = __float2half_rn(x[i]);
}
__global__ void cvt_w_kernel(const float* __restrict__ w) {
    int i = blockIdx.x * 256 + threadIdx.x;   // i = col*64 + c
    if (i < NKC * 64) {
        int col = i >> 6, c = i & 63;
        int k = col >> 6, d = col & 63;
        g_wt[i] = __float2half_rn(w[k * 4096 + c * 64 + d]);
    }
}

// ---------------- counting sort of edges by src bucket ----------------
__global__ void hist_kernel(const int* __restrict__ eidx) {
    int e = blockIdx.x * 256 + threadIdx.x;
    if (e < N_EDGES) atomicAdd(&g_bcnt[eidx[e] >> 4], 1u);
}
__global__ void scan_kernel() {
    __shared__ unsigned s[NBKT];
    int t = threadIdx.x;
    for (int i = t; i < NBKT; i += 1024) s[i] = g_bcnt[i];
    __syncthreads();
    for (int d = 1; d < NBKT; d <<= 1) {
        unsigned v[4];
        int j = 0;
        for (int i = t; i < NBKT; i += 1024, j++) v[j] = (i >= d) ? s[i - d] + s[i] : s[i];
        __syncthreads();
        j = 0;
        for (int i = t; i < NBKT; i += 1024, j++) s[i] = v[j];
        __syncthreads();
    }
    for (int i = t; i < NBKT; i += 1024) g_boff[i] = (i ? s[i - 1] : 0u);
}
__global__ void scatter_kernel(const int* __restrict__ eidx, const float* __restrict__ attr) {
    int e = blockIdx.x * 256 + threadIdx.x;
    if (e >= N_EDGES) return;
    int s = eidx[e];
    int d = eidx[N_EDGES + e];
    float f0 = attr[e * 3 + 0] * 3.f;
    float f1 = attr[e * 3 + 1] * 3.f;
    float f2 = attr[e * 3 + 2] * 3.f;
    float l0 = fminf(fmaxf(floorf(f0), 0.f), 2.f);
    float l1 = fminf(fmaxf(floorf(f1), 0.f), 2.f);
    float l2 = fminf(fmaxf(floorf(f2), 0.f), 2.f);
    int base_k = (int)l0 + 4 * (int)l1 + 16 * (int)l2;
    unsigned p = atomicAdd(&g_boff[s >> 4], 1u);
    g_rec[p] = make_float4(f0 - l0, f1 - l1, f2 - l2,
                           __uint_as_float((unsigned)s | ((unsigned)base_k << 20)));
    g_rdst[p] = d;
}

// ---------------- HMMA GEMM: g_xw[m, col] = sum_c xh[m,c] * wt[col,c] ----------------
#define APAD 72   // halves per smem row
#define CPAD 136  // C staging stride in halves

__global__ void __launch_bounds__(256) mm_kernel() {
    __shared__ __half sA[128 * APAD];
    __shared__ __half sB[128 * APAD];

    const int t = threadIdx.x;
    const int m0 = blockIdx.x * 128;
    const int col0 = blockIdx.y * 128;

    #pragma unroll
    for (int i = 0; i < 4; i++) {
        int f = t + i * 256;
        int m = f >> 3;
        int c8 = (f & 7) * 8;
        uint4 v = make_uint4(0, 0, 0, 0);
        if (m0 + m < N_NODES)
            v = *reinterpret_cast<const uint4*>(g_xh + (long long)(m0 + m) * 64 + c8);
        *reinterpret_cast<uint4*>(sA + m * APAD + c8) = v;
    }
    #pragma unroll
    for (int i = 0; i < 4; i++) {
        int f = t + i * 256;
        int j = f >> 3;
        int c8 = (f & 7) * 8;
        uint4 v = *reinterpret_cast<const uint4*>(g_wt + (long long)(col0 + j) * 64 + c8);
        *reinterpret_cast<uint4*>(sB + j * APAD + c8) = v;
    }
    __syncthreads();

    const int warp = t >> 5, lane = t & 31;
    const int wm = (warp & 3) * 32;
    const int wn = (warp >> 2) * 64;
    const int g = lane >> 2, tg = lane & 3;

    const uint32_t sAb = smem_u32(sA);
    const uint32_t sBb = smem_u32(sB);
    // ldmatrix lane addressing
    const int a_row = lane & 15, a_kc = (lane >> 4) * 8;            // A x4
    const int b_row = (lane & 7) + (lane >> 4) * 8;                 // B x4 (2 nf)
    const int b_kc  = ((lane >> 3) & 1) * 8;

    float acc[2][8][4];
    #pragma unroll
    for (int mf = 0; mf < 2; mf++)
        #pragma unroll
        for (int nf = 0; nf < 8; nf++)
            #pragma unroll
            for (int q = 0; q < 4; q++) acc[mf][nf][q] = 0.f;

    #pragma unroll
    for (int ks = 0; ks < 4; ks++) {
        int k0 = ks * 16;
        uint32_t a[2][4];
        #pragma unroll
        for (int mf = 0; mf < 2; mf++)
            ldsm_x4(a[mf], sAb + ((wm + mf * 16 + a_row) * APAD + k0 + a_kc) * 2);
        uint32_t b[8][2];
        #pragma unroll
        for (int np = 0; np < 4; np++) {
            uint32_t br[4];
            ldsm_x4(br, sBb + ((wn + np * 16 + b_row) * APAD + k0 + b_kc) * 2);
            b[2 * np][0] = br[0]; b[2 * np][1] = br[1];
            b[2 * np + 1][0] = br[2]; b[2 * np + 1][1] = br[3];
        }
        #pragma unroll
        for (int nf = 0; nf < 8; nf++) {
            hmma16816(acc[0][nf], a[0], b[nf]);
            hmma16816(acc[1][nf], a[1], b[nf]);
        }
    }

    __syncthreads();
    __half* sC = sA;   // reuse: 128*136*2 = 34816 B
    #pragma unroll
    for (int mf = 0; mf < 2; mf++) {
        #pragma unroll
        for (int nf = 0; nf < 8; nf++) {
            int c = wn + nf * 8 + 2 * tg;
            __half2 lo = __floats2half2_rn(acc[mf][nf][0], acc[mf][nf][1]);
            __half2 hi = __floats2half2_rn(acc[mf][nf][2], acc[mf][nf][3]);
            *reinterpret_cast<__half2*>(sC + (wm + mf * 16 + g)     * CPAD + c) = lo;
            *reinterpret_cast<__half2*>(sC + (wm + mf * 16 + g + 8) * CPAD + c) = hi;
        }
    }
    __syncthreads();
    #pragma unroll
    for (int i = 0; i < 8; i++) {
        int f = t + i * 256;
        int row = f >> 4;
        int q8 = (f & 15) * 8;
        if (m0 + row < N_NODES) {
            uint4 v = *reinterpret_cast<const uint4*>(sC + row * CPAD + q8);
            *reinterpret_cast<uint4*>(g_xw + (long long)(m0 + row) * NKC + col0 + q8) = v;
        }
    }
}

// ---------------- edge kernel: sorted records, gather + scatter-add ----------------
__global__ void __launch_bounds__(256) edge_kernel() {
    int t = threadIdx.x;
    int g = t >> 3;
    int l = t & 7;
    int e = blockIdx.x * 32 + g;
    if (e >= N_EDGES) return;

    float4 r = g_rec[e];
    int d = g_rdst[e];
    unsigned sp = __float_as_uint(r.w);
    int s = sp & 0xFFFFF;
    int base_k = sp >> 20;
    float t0 = r.x, t1 = r.y, t2 = r.z;
    float s0 = 1.f - t0, s1 = 1.f - t1, s2 = 1.f - t2;

    const __half* bp = g_xw + (long long)s * NKC + base_k * 64 + l * 8;

    uint4 q[8];
    #pragma unroll
    for (int b = 0; b < 8; b++) {
        int b0 = b & 1, b1 = (b >> 1) & 1, b2 = (b >> 2) & 1;
        q[b] = *reinterpret_cast<const uint4*>(bp + (b0 + 4 * b1 + 16 * b2) * 64);
    }

    float acc[8] = {0.f, 0.f, 0.f, 0.f, 0.f, 0.f, 0.f, 0.f};
    #pragma unroll
    for (int b = 0; b < 8; b++) {
        int b0 = b & 1, b1 = (b >> 1) & 1, b2 = (b >> 2) & 1;
        float wgt = (b0 ? t0 : s0) * (b1 ? t1 : s1) * (b2 ? t2 : s2);
        const __half2* h = reinterpret_cast<const __half2*>(&q[b]);
        #pragma unroll
        for (int j = 0; j < 4; j++) {
            float2 f = __half22float2(h[j]);
            acc[2 * j]     += wgt * f.x;
            acc[2 * j + 1] += wgt * f.y;
        }
    }
    float* ap = g_agg + (long long)d * 64 + l * 8;
    red_add_v4(ap,     acc[0], acc[1], acc[2], acc[3]);
    red_add_v4(ap + 4, acc[4], acc[5], acc[6], acc[7]);
    if (l == 0) red_add_f32(&g_cnt[d], 1.f);
}

// ---------------- node kernel ----------------
__global__ void __launch_bounds__(256) node_kernel(const float* __restrict__ x,
                                                   const float* __restrict__ root,
                                                   const float* __restrict__ bias) {
    __shared__ float rs[64 * 64];
    __shared__ float sred[128];
    int t = threadIdx.x;
    for (int i = t; i < 4096; i += 256) rs[i] = root[i];
    if (t < 128) sred[t] = 0.f;
    __syncthreads();

    int lane = t & 31, warp = t >> 5;
    int gw = blockIdx.x * 8 + warp;
    int nw = gridDim.x * 8;
    int d0 = lane, d1 = lane + 32;
    float b0 = bias[d0], b1 = bias[d1];
    float su0 = 0.f, sq0 = 0.f, su1 = 0.f, sq1 = 0.f;

    for (int n = gw; n < N_NODES; n += nw) {
        float ic = 1.f / fmaxf(g_cnt[n], 1.f);
        long long off = (long long)n * 64;
        float a0 = g_agg[off + d0] * ic + b0;
        float a1 = g_agg[off + d1] * ic + b1;
        const float* xr = x + off;
        float xv0 = xr[lane], xv1 = xr[lane + 32];
        #pragma unroll
        for (int c = 0; c < 32; c++) {
            float xa = __shfl_sync(0xffffffffu, xv0, c);
            a0 += xa * rs[c * 64 + d0];
            a1 += xa * rs[c * 64 + d1];
        }
        #pragma unroll
        for (int c = 0; c < 32; c++) {
            float xa = __shfl_sync(0xffffffffu, xv1, c);
            a0 += xa * rs[(c + 32) * 64 + d0];
            a1 += xa * rs[(c + 32) * 64 + d1];
        }
        float h0 = a0 > 0.f ? a0 : expm1f(a0);
        float h1 = a1 > 0.f ? a1 : expm1f(a1);
        g_h[off + d0] = h0;
        g_h[off + d1] = h1;
        su0 += h0; sq0 += h0 * h0;
        su1 += h1; sq1 += h1 * h1;
    }
    atomicAdd(&sred[d0], su0);
    atomicAdd(&sred[d1], su1);
    atomicAdd(&sred[64 + d0], sq0);
    atomicAdd(&sred[64 + d1], sq1);
    __syncthreads();
    if (t < 128) atomicAdd(&g_stats[t], sred[t]);
}

// ---------------- BN finalize ----------------
__global__ void stats_kernel(const float* __restrict__ gamma, const float* __restrict__ beta) {
    int d = threadIdx.x;
    if (d < 64) {
        float mean = g_stats[d] * (1.f / N_NODES);
        float var  = g_stats[64 + d] * (1.f / N_NODES) - mean * mean;
        float inv  = rsqrtf(var + EPS_BN);
        float sc   = gamma[d] * inv;
        g_scale[d] = sc;
        g_shift[d] = beta[d] - mean * sc;
    }
}

// ---------------- voxel max pool ----------------
__global__ void __launch_bounds__(256) pool_kernel(const float* __restrict__ pos,
                                                   const int* __restrict__ batch,
                                                   unsigned* __restrict__ outp) {
    int t = threadIdx.x;
    int lane = t & 31, warp = t >> 5;
    int gw = blockIdx.x * 8 + warp;
    int nw = gridDim.x * 8;
    int d0 = lane, d1 = lane + 32;
    float sc0 = g_scale[d0], sc1 = g_scale[d1];
    float sh0 = g_shift[d0], sh1 = g_shift[d1];

    for (int n = gw; n < N_NODES; n += nw) {
        float p0 = pos[n * 3 + 0], p1 = pos[n * 3 + 1], p2 = pos[n * 3 + 2];
        int v0 = min(max((int)floorf(p0 * (1.f / 32.f)), 0), 7);
        int v1 = min(max((int)floorf(p1 * (1.f / 32.f)), 0), 7);
        int v2 = min(max((int)floorf(p2 * (1.f / 32.f)), 0), 7);
        int cl = batch[n] * 512 + v0 * 64 + v1 * 8 + v2;
        long long off = (long long)n * 64;
        unsigned* op = outp + (long long)cl * 64;
        float y0 = g_h[off + d0] * sc0 + sh0;
        float y1 = g_h[off + d1] * sc1 + sh1;
        atomicMax(op + d0, encf(y0));
        atomicMax(op + d1, encf(y1));
    }
}

// ---------------- decode ----------------
__global__ void decode_kernel(float* __restrict__ out) {
    int i = blockIdx.x * 256 + threadIdx.x;
    if (i < NSEG * 64) {
        unsigned u = reinterpret_cast<unsigned*>(out)[i];
        out[i] = u ? decf(u) : 0.f;
    }
}

// ---------------- launch ----------------
extern "C" void kernel_launch(void* const* d_in, const int* in_sizes, int n_in,
                              void* d_out, int out_size) {
    const float* x      = (const float*)d_in[0];
    const int*   eidx   = (const int*)  d_in[1];
    const float* attr   = (const float*)d_in[2];
    const float* pos    = (const float*)d_in[3];
    const int*   batch  = (const int*)  d_in[4];
    const float* weight = (const float*)d_in[5];
    const float* root   = (const float*)d_in[6];
    const float* bias   = (const float*)d_in[7];
    const float* gamma  = (const float*)d_in[8];
    const float* beta   = (const float*)d_in[9];

    init_kernel<<<12500, 256>>>((unsigned*)d_out);
    cvt_x_kernel<<<(N_NODES * 64 + 255) / 256, 256>>>(x);
    cvt_w_kernel<<<(NKC * 64 + 255) / 256, 256>>>(weight);

    // edge sort (runs while queued before mm's output is needed)
    hist_kernel<<<(N_EDGES + 255) / 256, 256>>>(eidx);
    scan_kernel<<<1, 1024>>>();
    scatter_kernel<<<(N_EDGES + 255) / 256, 256>>>(eidx, attr);

    dim3 gg((N_NODES + 127) / 128, NKC / 128);   // 391 x 32
    mm_kernel<<<gg, 256>>>();

    edge_kernel<<<N_EDGES / 32, 256>>>();
    node_kernel<<<800, 256>>>(x, root, bias);
    stats_kernel<<<1, 64>>>(gamma, beta);
    pool_kernel<<<512, 256>>>(pos, batch, (unsigned*)d_out);
    decode_kernel<<<(NSEG * 64 + 255) / 256, 256>>>((float*)d_out);
}

// round 7
// speedup vs baseline: 1.2355x; 1.2355x over previous
#include <cuda_runtime.h>
#include <cuda_fp16.h>
#include <math.h>
#include <cstdint>

#define N_NODES 50000
#define N_EDGES 800000
#define XWC     4224        // 4096 spline cols + 64 root cols + 64 pad
#define NSEG    8192        // NB * GRID^3
#define EPS_BN  1e-5f

// ---------------- device scratch ----------------
__device__ __half g_xw[(long long)N_NODES * XWC];   // 422 MB fp16: x @ [W_k | root | 0]
__device__ __half g_xh[N_NODES * 64];               // x in fp16
__device__ __half g_wt[XWC * 64];                   // transposed weight [col][c] fp16
__device__ float g_agg[N_NODES * 64];
__device__ float g_h[N_NODES * 64];
__device__ float g_cnt[N_NODES];
__device__ float g_stats[128];
__device__ float g_scale[64];
__device__ float g_shift[64];

// ---------------- helpers ----------------
__device__ __forceinline__ unsigned encf(float f) {
    unsigned u = __float_as_uint(f);
    return (u & 0x80000000u) ? ~u : (u | 0x80000000u);
}
__device__ __forceinline__ float decf(unsigned e) {
    return __uint_as_float((e & 0x80000000u) ? (e ^ 0x80000000u) : ~e);
}
__device__ __forceinline__ void red_add_v4(float* p, float a, float b, float c, float d) {
    asm volatile("red.global.add.v4.f32 [%0], {%1, %2, %3, %4};"
                 :: "l"(p), "f"(a), "f"(b), "f"(c), "f"(d) : "memory");
}
__device__ __forceinline__ void red_add_f32(float* p, float a) {
    asm volatile("red.global.add.f32 [%0], %1;" :: "l"(p), "f"(a) : "memory");
}
__device__ __forceinline__ void hmma16816(float* d, const uint32_t* a, const uint32_t* b) {
    asm volatile(
        "mma.sync.aligned.m16n8k16.row.col.f32.f16.f16.f32 "
        "{%0,%1,%2,%3}, {%4,%5,%6,%7}, {%8,%9}, {%0,%1,%2,%3};"
        : "+f"(d[0]), "+f"(d[1]), "+f"(d[2]), "+f"(d[3])
        : "r"(a[0]), "r"(a[1]), "r"(a[2]), "r"(a[3]), "r"(b[0]), "r"(b[1]));
}
__device__ __forceinline__ void ldsm_x4(uint32_t* r, uint32_t addr) {
    asm volatile("ldmatrix.sync.aligned.m8n8.x4.shared.b16 {%0,%1,%2,%3}, [%4];"
                 : "=r"(r[0]), "=r"(r[1]), "=r"(r[2]), "=r"(r[3]) : "r"(addr));
}
__device__ __forceinline__ uint32_t smem_u32(const void* p) {
    uint32_t a;
    asm("{ .reg .u64 t; cvta.to.shared.u64 t, %1; cvt.u32.u64 %0, t; }" : "=r"(a) : "l"(p));
    return a;
}

// ---------------- init ----------------
__global__ void init_kernel(unsigned* __restrict__ out) {
    int i = blockIdx.x * 256 + threadIdx.x;
    if (i < N_NODES * 64) g_agg[i] = 0.f;
    if (i < N_NODES)      g_cnt[i] = 0.f;
    if (i < 128)          g_stats[i] = 0.f;
    if (i < NSEG * 64)    out[i] = 0u;
}

// ---------------- fp16 conversions ----------------
__global__ void cvt_x_kernel(const float* __restrict__ x) {
    int i = blockIdx.x * 256 + threadIdx.x;
    if (i < N_NODES * 64) g_xh[i] = __float2half_rn(x[i]);
}
__global__ void cvt_w_kernel(const float* __restrict__ w, const float* __restrict__ root) {
    int i = blockIdx.x * 256 + threadIdx.x;   // i = col*64 + c
    if (i < XWC * 64) {
        int col = i >> 6, c = i & 63;
        float v = 0.f;
        if (col < 4096) {
            int k = col >> 6, d = col & 63;
            v = w[k * 4096 + c * 64 + d];
        } else if (col < 4160) {
            v = root[c * 64 + (col - 4096)];
        }
        g_wt[i] = __float2half_rn(v);
    }
}

// ---------------- HMMA GEMM: g_xw[m, col] = sum_c xh[m,c] * wt[col,c] ----------------
#define APAD 72   // halves per smem row
#define CPAD 136  // C staging stride in halves

__global__ void __launch_bounds__(256) mm_kernel() {
    __shared__ __half sA[128 * APAD];
    __shared__ __half sB[128 * APAD];

    const int t = threadIdx.x;
    const int m0 = blockIdx.x * 128;
    const int col0 = blockIdx.y * 128;

    #pragma unroll
    for (int i = 0; i < 4; i++) {
        int f = t + i * 256;
        int m = f >> 3;
        int c8 = (f & 7) * 8;
        uint4 v = make_uint4(0, 0, 0, 0);
        if (m0 + m < N_NODES)
            v = *reinterpret_cast<const uint4*>(g_xh + (long long)(m0 + m) * 64 + c8);
        *reinterpret_cast<uint4*>(sA + m * APAD + c8) = v;
    }
    #pragma unroll
    for (int i = 0; i < 4; i++) {
        int f = t + i * 256;
        int j = f >> 3;
        int c8 = (f & 7) * 8;
        uint4 v = *reinterpret_cast<const uint4*>(g_wt + (long long)(col0 + j) * 64 + c8);
        *reinterpret_cast<uint4*>(sB + j * APAD + c8) = v;
    }
    __syncthreads();

    const int warp = t >> 5, lane = t & 31;
    const int wm = (warp & 3) * 32;
    const int wn = (warp >> 2) * 64;
    const int g = lane >> 2, tg = lane & 3;

    const uint32_t sAb = smem_u32(sA);
    const uint32_t sBb = smem_u32(sB);
    const int a_row = lane & 15, a_kc = (lane >> 4) * 8;
    const int b_row = (lane & 7) + (lane >> 4) * 8;
    const int b_kc  = ((lane >> 3) & 1) * 8;

    float acc[2][8][4];
    #pragma unroll
    for (int mf = 0; mf < 2; mf++)
        #pragma unroll
        for (int nf = 0; nf < 8; nf++)
            #pragma unroll
            for (int q = 0; q < 4; q++) acc[mf][nf][q] = 0.f;

    #pragma unroll
    for (int ks = 0; ks < 4; ks++) {
        int k0 = ks * 16;
        uint32_t a[2][4];
        #pragma unroll
        for (int mf = 0; mf < 2; mf++)
            ldsm_x4(a[mf], sAb + ((wm + mf * 16 + a_row) * APAD + k0 + a_kc) * 2);
        uint32_t b[8][2];
        #pragma unroll
        for (int np = 0; np < 4; np++) {
            uint32_t br[4];
            ldsm_x4(br, sBb + ((wn + np * 16 + b_row) * APAD + k0 + b_kc) * 2);
            b[2 * np][0] = br[0]; b[2 * np][1] = br[1];
            b[2 * np + 1][0] = br[2]; b[2 * np + 1][1] = br[3];
        }
        #pragma unroll
        for (int nf = 0; nf < 8; nf++) {
            hmma16816(acc[0][nf], a[0], b[nf]);
            hmma16816(acc[1][nf], a[1], b[nf]);
        }
    }

    __syncthreads();
    __half* sC = sA;   // reuse: 128*136*2 = 34816 B
    #pragma unroll
    for (int mf = 0; mf < 2; mf++) {
        #pragma unroll
        for (int nf = 0; nf < 8; nf++) {
            int c = wn + nf * 8 + 2 * tg;
            __half2 lo = __floats2half2_rn(acc[mf][nf][0], acc[mf][nf][1]);
            __half2 hi = __floats2half2_rn(acc[mf][nf][2], acc[mf][nf][3]);
            *reinterpret_cast<__half2*>(sC + (wm + mf * 16 + g)     * CPAD + c) = lo;
            *reinterpret_cast<__half2*>(sC + (wm + mf * 16 + g + 8) * CPAD + c) = hi;
        }
    }
    __syncthreads();
    #pragma unroll
    for (int i = 0; i < 8; i++) {
        int f = t + i * 256;
        int row = f >> 4;
        int q8 = (f & 15) * 8;
        if (m0 + row < N_NODES) {
            uint4 v = *reinterpret_cast<const uint4*>(sC + row * CPAD + q8);
            *reinterpret_cast<uint4*>(g_xw + (long long)(m0 + row) * XWC + col0 + q8) = v;
        }
    }
}

// ---------------- edge kernel: spline-weighted gather + scatter-add ----------------
__global__ void __launch_bounds__(256) edge_kernel(const int* __restrict__ eidx,
                                                   const float* __restrict__ attr) {
    int t = threadIdx.x;
    int g = t >> 3;
    int l = t & 7;
    int e = blockIdx.x * 32 + g;
    if (e >= N_EDGES) return;

    int s = eidx[e];
    int d = eidx[N_EDGES + e];

    float f0 = attr[e * 3 + 0] * 3.f;
    float f1 = attr[e * 3 + 1] * 3.f;
    float f2 = attr[e * 3 + 2] * 3.f;
    float l0 = fminf(fmaxf(floorf(f0), 0.f), 2.f);
    float l1 = fminf(fmaxf(floorf(f1), 0.f), 2.f);
    float l2 = fminf(fmaxf(floorf(f2), 0.f), 2.f);
    float t0 = f0 - l0, t1 = f1 - l1, t2 = f2 - l2;
    float s0 = 1.f - t0, s1 = 1.f - t1, s2 = 1.f - t2;
    int base_k = (int)l0 + 4 * (int)l1 + 16 * (int)l2;

    const __half* bp = g_xw + (long long)s * XWC + base_k * 64 + l * 8;

    uint4 q[8];
    #pragma unroll
    for (int b = 0; b < 8; b++) {
        int b0 = b & 1, b1 = (b >> 1) & 1, b2 = (b >> 2) & 1;
        q[b] = *reinterpret_cast<const uint4*>(bp + (b0 + 4 * b1 + 16 * b2) * 64);
    }

    float acc[8] = {0.f, 0.f, 0.f, 0.f, 0.f, 0.f, 0.f, 0.f};
    #pragma unroll
    for (int b = 0; b < 8; b++) {
        int b0 = b & 1, b1 = (b >> 1) & 1, b2 = (b >> 2) & 1;
        float wgt = (b0 ? t0 : s0) * (b1 ? t1 : s1) * (b2 ? t2 : s2);
        const __half2* h = reinterpret_cast<const __half2*>(&q[b]);
        #pragma unroll
        for (int j = 0; j < 4; j++) {
            float2 f = __half22float2(h[j]);
            acc[2 * j]     += wgt * f.x;
            acc[2 * j + 1] += wgt * f.y;
        }
    }
    float* ap = g_agg + (long long)d * 64 + l * 8;
    red_add_v4(ap,     acc[0], acc[1], acc[2], acc[3]);
    red_add_v4(ap + 4, acc[4], acc[5], acc[6], acc[7]);
    if (l == 0) red_add_f32(&g_cnt[d], 1.f);
}

// ---------------- node kernel: elementwise h = agg/cnt + xroot + bias, ELU, stats ----------
__global__ void __launch_bounds__(256) node_kernel(const float* __restrict__ bias) {
    __shared__ float sred[128];
    int t = threadIdx.x;
    if (t < 128) sred[t] = 0.f;
    __syncthreads();

    int lane = t & 31, warp = t >> 5;
    int gw = blockIdx.x * 8 + warp;
    int nw = gridDim.x * 8;
    int d0 = lane, d1 = lane + 32;
    float b0 = bias[d0], b1 = bias[d1];
    float su0 = 0.f, sq0 = 0.f, su1 = 0.f, sq1 = 0.f;

    for (int n = gw; n < N_NODES; n += nw) {
        float ic = 1.f / fmaxf(g_cnt[n], 1.f);
        long long off = (long long)n * 64;
        const __half* xr = g_xw + (long long)n * XWC + 4096;
        float r0 = __half2float(xr[d0]);
        float r1 = __half2float(xr[d1]);
        float a0 = g_agg[off + d0] * ic + b0 + r0;
        float a1 = g_agg[off + d1] * ic + b1 + r1;
        float h0 = a0 > 0.f ? a0 : expm1f(a0);
        float h1 = a1 > 0.f ? a1 : expm1f(a1);
        g_h[off + d0] = h0;
        g_h[off + d1] = h1;
        su0 += h0; sq0 += h0 * h0;
        su1 += h1; sq1 += h1 * h1;
    }
    atomicAdd(&sred[d0], su0);
    atomicAdd(&sred[d1], su1);
    atomicAdd(&sred[64 + d0], sq0);
    atomicAdd(&sred[64 + d1], sq1);
    __syncthreads();
    if (t < 128) atomicAdd(&g_stats[t], sred[t]);
}

// ---------------- BN finalize ----------------
__global__ void stats_kernel(const float* __restrict__ gamma, const float* __restrict__ beta) {
    int d = threadIdx.x;
    if (d < 64) {
        float mean = g_stats[d] * (1.f / N_NODES);
        float var  = g_stats[64 + d] * (1.f / N_NODES) - mean * mean;
        float inv  = rsqrtf(var + EPS_BN);
        float sc   = gamma[d] * inv;
        g_scale[d] = sc;
        g_shift[d] = beta[d] - mean * sc;
    }
}

// ---------------- voxel max pool ----------------
__global__ void __launch_bounds__(256) pool_kernel(const float* __restrict__ pos,
                                                   const int* __restrict__ batch,
                                                   unsigned* __restrict__ outp) {
    int t = threadIdx.x;
    int lane = t & 31, warp = t >> 5;
    int gw = blockIdx.x * 8 + warp;
    int nw = gridDim.x * 8;
    int d0 = lane, d1 = lane + 32;
    float sc0 = g_scale[d0], sc1 = g_scale[d1];
    float sh0 = g_shift[d0], sh1 = g_shift[d1];

    for (int n = gw; n < N_NODES; n += nw) {
        float p0 = pos[n * 3 + 0], p1 = pos[n * 3 + 1], p2 = pos[n * 3 + 2];
        int v0 = min(max((int)floorf(p0 * (1.f / 32.f)), 0), 7);
        int v1 = min(max((int)floorf(p1 * (1.f / 32.f)), 0), 7);
        int v2 = min(max((int)floorf(p2 * (1.f / 32.f)), 0), 7);
        int cl = batch[n] * 512 + v0 * 64 + v1 * 8 + v2;
        long long off = (long long)n * 64;
        unsigned* op = outp + (long long)cl * 64;
        float y0 = g_h[off + d0] * sc0 + sh0;
        float y1 = g_h[off + d1] * sc1 + sh1;
        atomicMax(op + d0, encf(y0));
        atomicMax(op + d1, encf(y1));
    }
}

// ---------------- decode ----------------
__global__ void decode_kernel(float* __restrict__ out) {
    int i = blockIdx.x * 256 + threadIdx.x;
    if (i < NSEG * 64) {
        unsigned u = reinterpret_cast<unsigned*>(out)[i];
        out[i] = u ? decf(u) : 0.f;
    }
}

// ---------------- launch ----------------
extern "C" void kernel_launch(void* const* d_in, const int* in_sizes, int n_in,
                              void* d_out, int out_size) {
    const float* x      = (const float*)d_in[0];
    const int*   eidx   = (const int*)  d_in[1];
    const float* attr   = (const float*)d_in[2];
    const float* pos    = (const float*)d_in[3];
    const int*   batch  = (const int*)  d_in[4];
    const float* weight = (const float*)d_in[5];
    const float* root   = (const float*)d_in[6];
    const float* bias   = (const float*)d_in[7];
    const float* gamma  = (const float*)d_in[8];
    const float* beta   = (const float*)d_in[9];

    init_kernel<<<12500, 256>>>((unsigned*)d_out);
    cvt_x_kernel<<<(N_NODES * 64 + 255) / 256, 256>>>(x);
    cvt_w_kernel<<<(XWC * 64 + 255) / 256, 256>>>(weight, root);

    dim3 gg((N_NODES + 127) / 128, XWC / 128);   // 391 x 33
    mm_kernel<<<gg, 256>>>();

    edge_kernel<<<N_EDGES / 32, 256>>>(eidx, attr);
    node_kernel<<<800, 256>>>(bias);
    stats_kernel<<<1, 64>>>(gamma, beta);
    pool_kernel<<<512, 256>>>(pos, batch, (unsigned*)d_out);
    decode_kernel<<<(NSEG * 64 + 255) / 256, 256>>>((float*)d_out);
}